// round 11
// baseline (speedup 1.0000x reference)
#include <cuda_runtime.h>
#include <cuda_bf16.h>
#include <math.h>
#include <stdint.h>

// Problem constants
#define BB 64      // batch
#define TT 256     // time steps
#define DD 1024    // input dim
#define HH 1024    // hidden dim
#define LL 4       // layers
#define GG 4096    // 4*H gate width
#define MM (TT*BB) // 16384 rows of the big GEMM
#define NBLK 128   // persistent grid size for recurrence

// ---------------------------------------------------------------------------
// Scratch (static device globals; no runtime allocation allowed)
// ---------------------------------------------------------------------------
__device__ float g_gx[(size_t)MM * GG];              // [T*B, 4H] gate pre-activations
__device__ __nv_bfloat16 g_ahi[(size_t)MM * DD];     // activations hi, [m][k]
__device__ __nv_bfloat16 g_alo[(size_t)MM * DD];     // activations lo
__device__ __nv_bfloat16 g_wthi[(size_t)GG * DD];    // Wx^T hi, [n][k]
__device__ __nv_bfloat16 g_wtlo[(size_t)GG * DD];    // Wx^T lo
__device__ __nv_bfloat16 g_whthi[(size_t)GG * HH];   // Wh^T hi, [n][k]
__device__ __nv_bfloat16 g_whtlo[(size_t)GG * HH];   // Wh^T lo
__device__ __nv_bfloat16 g_hbhi[2][BB][HH];          // h double buffer, hi
__device__ __nv_bfloat16 g_hblo[2][BB][HH];          // h double buffer, lo
__device__ unsigned g_bar_count;                     // grid barrier (zero-init)
__device__ volatile unsigned g_bar_gen;

// ---------------------------------------------------------------------------
// Helpers
// ---------------------------------------------------------------------------
__device__ __forceinline__ void bsplit(float v, __nv_bfloat16& hi, __nv_bfloat16& lo) {
    hi = __float2bfloat16(v);
    lo = __float2bfloat16(v - __bfloat162float(hi));
}
__device__ __forceinline__ uint32_t smem_u32(const void* p) {
    uint32_t a;
    asm("{ .reg .u64 t; cvta.to.shared.u64 t, %1; cvt.u32.u64 %0, t; }" : "=r"(a) : "l"(p));
    return a;
}
__device__ __forceinline__ void ldsm4(uint32_t* r, uint32_t addr) {
    asm volatile("ldmatrix.sync.aligned.m8n8.x4.shared.b16 {%0,%1,%2,%3}, [%4];"
                 : "=r"(r[0]), "=r"(r[1]), "=r"(r[2]), "=r"(r[3]) : "r"(addr));
}
__device__ __forceinline__ void mma_bf16(float* d, const uint32_t* a,
                                         uint32_t b0, uint32_t b1) {
    asm volatile(
        "mma.sync.aligned.m16n8k16.row.col.f32.bf16.bf16.f32 "
        "{%0,%1,%2,%3},{%4,%5,%6,%7},{%8,%9},{%0,%1,%2,%3};"
        : "+f"(d[0]), "+f"(d[1]), "+f"(d[2]), "+f"(d[3])
        : "r"(a[0]), "r"(a[1]), "r"(a[2]), "r"(a[3]), "r"(b0), "r"(b1));
}
#define CP16(d, s) asm volatile("cp.async.cg.shared.global [%0], [%1], 16;" \
                                :: "r"(d), "l"(s) : "memory")
#define CP_COMMIT() asm volatile("cp.async.commit_group;" ::: "memory")
#define CP_WAIT1()  asm volatile("cp.async.wait_group 1;" ::: "memory")
#define CP_WAIT0()  asm volatile("cp.async.wait_group 0;" ::: "memory")

// ---------------------------------------------------------------------------
// Software grid barrier (all NBLK blocks co-resident)
// ---------------------------------------------------------------------------
__device__ __forceinline__ void grid_sync() {
    __syncthreads();
    if (threadIdx.x == 0) {
        __threadfence();
        unsigned gen = g_bar_gen;
        if (atomicAdd(&g_bar_count, 1u) == NBLK - 1) {
            g_bar_count = 0;
            __threadfence();
            g_bar_gen = gen + 1;
        } else {
            while (g_bar_gen == gen) { }
            __threadfence();
        }
    }
    __syncthreads();
}

// ---------------------------------------------------------------------------
// prep_x: x [B,T,D] fp32 -> g_ahi/g_alo [m=t*B+b][k] bf16 hi/lo
// ---------------------------------------------------------------------------
__global__ __launch_bounds__(256) void prep_x_kernel(const float* __restrict__ x) {
    size_t id = (size_t)blockIdx.x * 256 + threadIdx.x;   // float4 index
    int m = (int)(id >> 8);
    int d = (int)(id & 255) * 4;
    int b = m & (BB - 1), t = m >> 6;
    float4 v = *(const float4*)(x + ((size_t)b * TT + t) * DD + d);
    __nv_bfloat16 h0, h1, h2, h3, l0, l1, l2, l3;
    bsplit(v.x, h0, l0); bsplit(v.y, h1, l1);
    bsplit(v.z, h2, l2); bsplit(v.w, h3, l3);
    size_t o = (size_t)m * DD + d;
    *(__nv_bfloat162*)&g_ahi[o]     = __nv_bfloat162(h0, h1);
    *(__nv_bfloat162*)&g_ahi[o + 2] = __nv_bfloat162(h2, h3);
    *(__nv_bfloat162*)&g_alo[o]     = __nv_bfloat162(l0, l1);
    *(__nv_bfloat162*)&g_alo[o + 2] = __nv_bfloat162(l2, l3);
}

// ---------------------------------------------------------------------------
// prep_wt: W [1024 k][4096 n] fp32 -> W^T hi/lo [n][k] bf16 (transpose+split)
// sel=0 -> g_wthi/g_wtlo (Wx), sel=1 -> g_whthi/g_whtlo (Wh)
// ---------------------------------------------------------------------------
__global__ __launch_bounds__(256) void prep_wt_kernel(const float* __restrict__ W,
                                                      int sel) {
    __shared__ float tile[32][33];
    __nv_bfloat16* hi = sel ? g_whthi : g_wthi;
    __nv_bfloat16* lo = sel ? g_whtlo : g_wtlo;
    int n0 = blockIdx.x * 32, k0 = blockIdx.y * 32;
    int ty = threadIdx.x >> 5, tx = threadIdx.x & 31;
#pragma unroll
    for (int i = 0; i < 4; ++i) {
        int kk = ty + i * 8;
        tile[kk][tx] = W[(size_t)(k0 + kk) * GG + n0 + tx];
    }
    __syncthreads();
#pragma unroll
    for (int i = 0; i < 4; ++i) {
        int a = ty + i * 8;                 // local n
        float v = tile[tx][a];
        __nv_bfloat16 h, l; bsplit(v, h, l);
        size_t o = (size_t)(n0 + a) * DD + k0 + tx;
        hi[o] = h;
        lo[o] = l;
    }
}

// ---------------------------------------------------------------------------
// Tensor-core input GEMM via mma.sync (HMMA), 3-term bf16 split.
// Block tile 128x128, 8 warps x (32x64), k-chunks of 64, cp.async pipelined.
// ---------------------------------------------------------------------------
#define G_ARR  (128 * 72)           // halves per array
#define G_BUFH (4 * G_ARR)          // halves per buffer (Ahi,Alo,Bhi,Blo)
#define G_SMEM (2 * G_BUFH * 2)     // bytes (double buffered) = 147456

__global__ __launch_bounds__(256) void gemm_tc_kernel(const float* __restrict__ bias) {
    extern __shared__ char sm[];
    uint32_t sbase = smem_u32(sm);
    const int tid = threadIdx.x, lane = tid & 31, wid = tid >> 5;
    const int wm = wid >> 1, wn = wid & 1;
    const int m0 = blockIdx.y * 128, n0 = blockIdx.x * 128;

    float acc[2][8][4];
#pragma unroll
    for (int f = 0; f < 2; ++f)
#pragma unroll
        for (int q = 0; q < 8; ++q)
#pragma unroll
            for (int e = 0; e < 4; ++e) acc[f][q][e] = 0.0f;

    const uint32_t lrow = lane & 15, lcolq = (lane >> 4) * 8;

#define G_STAGE(kc) do {                                                      \
    uint32_t dstb = sbase + ((kc) & 1) * (G_BUFH * 2);                        \
    _Pragma("unroll")                                                         \
    for (int i = 0; i < 4; ++i) {                                             \
        int idx = tid + i * 256;                                              \
        int row = idx >> 3, q = idx & 7;                                      \
        size_t ga = (size_t)(m0 + row) * DD + (kc) * 64 + q * 8;              \
        size_t gb = (size_t)(n0 + row) * DD + (kc) * 64 + q * 8;              \
        uint32_t off = (uint32_t)(row * 72 + q * 8) * 2;                      \
        CP16(dstb + 0 * (G_ARR * 2) + off, g_ahi + ga);                       \
        CP16(dstb + 1 * (G_ARR * 2) + off, g_alo + ga);                       \
        CP16(dstb + 2 * (G_ARR * 2) + off, g_wthi + gb);                      \
        CP16(dstb + 3 * (G_ARR * 2) + off, g_wtlo + gb);                      \
    }                                                                         \
} while (0)

    G_STAGE(0); CP_COMMIT();

    for (int kc = 0; kc < 16; ++kc) {
        if (kc < 15) { G_STAGE(kc + 1); CP_COMMIT(); CP_WAIT1(); }
        else         { CP_WAIT0(); }
        __syncthreads();

        uint32_t bufb = sbase + (kc & 1) * (G_BUFH * 2);
#pragma unroll
        for (int s = 0; s < 4; ++s) {
            uint32_t koff = (s * 16 + lcolq) * 2;
            uint32_t ahi[2][4], alo[2][4];
#pragma unroll
            for (int f = 0; f < 2; ++f) {
                uint32_t a = bufb + (uint32_t)((wm * 32 + f * 16 + lrow) * 72) * 2 + koff;
                ldsm4(ahi[f], a);
                ldsm4(alo[f], a + G_ARR * 2);
            }
#pragma unroll
            for (int q = 0; q < 4; ++q) {
                uint32_t b = bufb + 2 * (G_ARR * 2)
                           + (uint32_t)((wn * 64 + q * 16 + lrow) * 72) * 2 + koff;
                uint32_t bh[4], bl[4];
                ldsm4(bh, b);
                ldsm4(bl, b + G_ARR * 2);
#pragma unroll
                for (int f = 0; f < 2; ++f) {
                    mma_bf16(acc[f][2 * q],     ahi[f], bh[0], bh[2]);
                    mma_bf16(acc[f][2 * q + 1], ahi[f], bh[1], bh[3]);
                    mma_bf16(acc[f][2 * q],     ahi[f], bl[0], bl[2]);
                    mma_bf16(acc[f][2 * q + 1], ahi[f], bl[1], bl[3]);
                    mma_bf16(acc[f][2 * q],     alo[f], bh[0], bh[2]);
                    mma_bf16(acc[f][2 * q + 1], alo[f], bh[1], bh[3]);
                }
            }
        }
        __syncthreads();
    }

    // epilogue: bias add + store
#pragma unroll
    for (int f = 0; f < 2; ++f) {
        int row = m0 + wm * 32 + f * 16 + (lane >> 2);
#pragma unroll
        for (int q = 0; q < 8; ++q) {
            int col = n0 + wn * 64 + q * 8 + (lane & 3) * 2;
            float2 bv = *(const float2*)&bias[col];
            *(float2*)&g_gx[(size_t)row * GG + col] =
                make_float2(acc[f][q][0] + bv.x, acc[f][q][1] + bv.y);
            *(float2*)&g_gx[(size_t)(row + 8) * GG + col] =
                make_float2(acc[f][q][2] + bv.x, acc[f][q][3] + bv.y);
        }
    }
#undef G_STAGE
}

// ---------------------------------------------------------------------------
// Persistent tensor-core recurrence, 256 threads (8 warps = 2m x 4k),
// warp tile 32m x 32n (full block n). Block b owns 8 hidden cols -> 32 gate
// cols. Wh^T slice (hi+lo, 132 KB) RESIDENT in smem for the whole layer.
// h staged via double-buffered cp.async in k-chunks of 64. Partials [4][64][36]
// reduced in the cell epilogue. One grid barrier per step.
// ---------------------------------------------------------------------------
#define RB_ROW 1032                          // B row halves (1024+8); 2064B stride
#define RB_HI  0
#define RB_LO  (32 * RB_ROW)                 // halves
#define RB_BYTES (2 * 32 * RB_ROW * 2)       // 132096 B
#define RA_OFF  RB_BYTES                     // A staging base (bytes)
#define RA_ROW 72
#define RA_LO  (64 * RA_ROW)                 // halves within buffer
#define RA_BUFH (2 * 64 * RA_ROW)            // 9216 halves per buffer
#define RA_BYTES (2 * RA_BUFH * 2)           // 36864 B (double buffered)
#define RP_OFF (RA_OFF + RA_BYTES)           // partials: [4][64][36] fp32
#define RP_BYTES (4 * 64 * 36 * 4)           // 36864 B
#define RC_OFF (RP_OFF + RP_BYTES)           // cell state [64][8] fp32
#define R_SMEM (RC_OFF + 64 * 8 * 4)         // 207872 B total

__global__ __launch_bounds__(256) void layer_recur_kernel(
    float* __restrict__ outp, int is_last)
{
    extern __shared__ char sm[];
    float* part = (float*)(sm + RP_OFF);
    float* csm  = (float*)(sm + RC_OFF);
    uint32_t sbase = smem_u32(sm);

    const int tid = threadIdx.x, lane = tid & 31, wid = tid >> 5;
    const int kh = wid & 3, wm = wid >> 2;
    const int j0h = blockIdx.x * 8;

    const uint32_t lrow = lane & 15, lcolq = (lane >> 4) * 8;
    const int er = tid >> 2, ec = (tid & 3) * 2;

    // ---- load resident Wh^T slice: rows = 32 gate cols, 1024 k halves each
    {
        for (int it = 0; it < 16; ++it) {
            int idx = tid + it * 256;            // float4 units: 32 rows x 128
            int r = idx >> 7, q = idx & 127;
            int gc = (r >> 3) * 1024 + j0h + (r & 7);
            uint32_t off = (uint32_t)(r * RB_ROW + q * 8) * 2;
            *(uint4*)(sm + off) =
                *(const uint4*)(g_whthi + (size_t)gc * HH + q * 8);
            *(uint4*)(sm + RB_LO * 2 + off) =
                *(const uint4*)(g_whtlo + (size_t)gc * HH + q * 8);
        }
    }
    // zero cell state (256 threads x 2)
    csm[er * 8 + ec]     = 0.0f;
    csm[er * 8 + ec + 1] = 0.0f;
    __syncthreads();

    for (int t = 0; t < TT; ++t) {
        // prefetch input-side gates: 2 cols per thread x 4 chunks
        float2 gxv[4];
        {
            size_t base = ((size_t)t * BB + er) * GG + j0h + ec;
#pragma unroll
            for (int c = 0; c < 4; ++c)
                gxv[c] = *(const float2*)&g_gx[base + (size_t)c * 1024];
        }

        float acc[2][4][4];
#pragma unroll
        for (int f = 0; f < 2; ++f)
#pragma unroll
            for (int q = 0; q < 4; ++q)
#pragma unroll
                for (int e = 0; e < 4; ++e) acc[f][q][e] = 0.0f;

        if (t > 0) {
            const __nv_bfloat16* hhi = &g_hbhi[t & 1][0][0];
            const __nv_bfloat16* hlo = &g_hblo[t & 1][0][0];

#define R_STAGE(kc) do {                                                      \
    uint32_t dstb = sbase + RA_OFF + ((kc) & 1) * (RA_BUFH * 2);              \
    _Pragma("unroll")                                                         \
    for (int i = 0; i < 2; ++i) {                                             \
        int idx = tid + i * 256;                                              \
        int row = idx >> 3, q = idx & 7;                                      \
        size_t gs = (size_t)row * HH + (kc) * 64 + q * 8;                     \
        uint32_t off = (uint32_t)(row * RA_ROW + q * 8) * 2;                  \
        CP16(dstb + off, hhi + gs);                                           \
        CP16(dstb + RA_LO * 2 + off, hlo + gs);                               \
    }                                                                         \
} while (0)

            R_STAGE(0); CP_COMMIT();

            for (int kc = 0; kc < 16; ++kc) {
                if (kc < 15) { R_STAGE(kc + 1); CP_COMMIT(); CP_WAIT1(); }
                else         { CP_WAIT0(); }
                __syncthreads();

                uint32_t bufb = sbase + RA_OFF + (kc & 1) * (RA_BUFH * 2);
                uint32_t koff = (uint32_t)(kh * 16 + lcolq) * 2;

                // A fragments (2 m-tiles, hi+lo)
                uint32_t ahi[2][4], alo[2][4];
#pragma unroll
                for (int f = 0; f < 2; ++f) {
                    uint32_t a = bufb
                               + (uint32_t)((wm * 32 + f * 16 + lrow) * RA_ROW) * 2
                               + koff;
                    ldsm4(ahi[f], a);
                    ldsm4(alo[f], a + RA_LO * 2);
                }

                // B fragments from resident Wh (2 n-tiles, hi+lo); global k
                uint32_t kglob = (uint32_t)(kc * 64 + kh * 16 + lcolq) * 2;
#pragma unroll
                for (int nt = 0; nt < 2; ++nt) {
                    uint32_t b = sbase
                               + (uint32_t)((nt * 16 + lrow) * RB_ROW) * 2 + kglob;
                    uint32_t bh[4], bl[4];
                    ldsm4(bh, b);
                    ldsm4(bl, b + RB_LO * 2);
#pragma unroll
                    for (int f = 0; f < 2; ++f) {
                        mma_bf16(acc[f][2 * nt],     ahi[f], bh[0], bh[2]);
                        mma_bf16(acc[f][2 * nt + 1], ahi[f], bh[1], bh[3]);
                        mma_bf16(acc[f][2 * nt],     ahi[f], bl[0], bl[2]);
                        mma_bf16(acc[f][2 * nt + 1], ahi[f], bl[1], bl[3]);
                        mma_bf16(acc[f][2 * nt],     alo[f], bh[0], bh[2]);
                        mma_bf16(acc[f][2 * nt + 1], alo[f], bh[1], bh[3]);
                    }
                }
                __syncthreads();
            }
#undef R_STAGE
        }

        // store partial sums: part[kh][row][col]  (cols 0..31)
        {
            int prow = wm * 32 + (lane >> 2);
            int pcol = (lane & 3) * 2;
            float* pb = part + kh * (64 * 36);
#pragma unroll
            for (int f = 0; f < 2; ++f)
#pragma unroll
                for (int q = 0; q < 4; ++q) {
                    float* p = pb + (size_t)(prow + f * 16) * 36 + q * 8 + pcol;
                    p[0] = acc[f][q][0];
                    p[1] = acc[f][q][1];
                    p[8 * 36]     = acc[f][q][2];
                    p[8 * 36 + 1] = acc[f][q][3];
                }
        }
        __syncthreads();

        // LSTM cell: 2 elements/thread; gate order i,f,g,o by chunk
        int nb = (t + 1) & 1;
#pragma unroll
        for (int i = 0; i < 2; ++i) {
            int cc = ec + i;
            float z[4];
#pragma unroll
            for (int c = 0; c < 4; ++c) {
                int lc = c * 8 + cc;
                float s = ((const float*)&gxv[c])[i];
#pragma unroll
                for (int p = 0; p < 4; ++p)
                    s += part[p * (64 * 36) + er * 36 + lc];
                z[c] = s;
            }
            float ig = 1.0f / (1.0f + expf(-z[0]));
            float fg = 1.0f / (1.0f + expf(-z[1]));
            float gg = tanhf(z[2]);
            float og = 1.0f / (1.0f + expf(-z[3]));
            float cv = fg * csm[er * 8 + cc] + ig * gg;
            float hv = og * tanhf(cv);
            csm[er * 8 + cc] = cv;
            __nv_bfloat16 hi, lo; bsplit(hv, hi, lo);
            g_hbhi[nb][er][j0h + cc] = hi;
            g_hblo[nb][er][j0h + cc] = lo;
            if (is_last) {
                outp[(size_t)t * (BB * HH) + (size_t)er * HH + j0h + cc] = hv;
            } else {
                size_t o = ((size_t)t * BB + er) * DD + j0h + cc;
                g_ahi[o] = hi;
                g_alo[o] = lo;
            }
        }

        grid_sync();   // publish h(t) before step t+1
    }
}

// ---------------------------------------------------------------------------
// Host launcher: 1 + 4*(2 preps + gemm + recur) = 17 graph nodes
// Inputs: x [B,T,D], Wx [L,D,4H], Wh [L,H,4H], b [L,4H]. Output [T,B,H] fp32.
// ---------------------------------------------------------------------------
extern "C" void kernel_launch(void* const* d_in, const int* in_sizes, int n_in,
                              void* d_out, int out_size)
{
    const float* x    = (const float*)d_in[0];
    const float* Wx   = (const float*)d_in[1];
    const float* Wh   = (const float*)d_in[2];
    const float* bias = (const float*)d_in[3];
    float* out = (float*)d_out;

    cudaFuncSetAttribute(gemm_tc_kernel,
                         cudaFuncAttributeMaxDynamicSharedMemorySize, G_SMEM);
    cudaFuncSetAttribute(layer_recur_kernel,
                         cudaFuncAttributeMaxDynamicSharedMemorySize, R_SMEM);

    prep_x_kernel<<<MM * DD / 4 / 256, 256>>>(x);

    for (int l = 0; l < LL; ++l) {
        prep_wt_kernel<<<dim3(GG / 32, DD / 32), 256>>>(Wx + (size_t)l * DD * GG, 0);
        prep_wt_kernel<<<dim3(GG / 32, HH / 32), 256>>>(Wh + (size_t)l * HH * GG, 1);

        gemm_tc_kernel<<<dim3(GG / 128, MM / 128), 256, G_SMEM>>>(
            bias + (size_t)l * GG);

        layer_recur_kernel<<<NBLK, 256, R_SMEM>>>(out, (l == LL - 1) ? 1 : 0);
    }
}